// round 6
// baseline (speedup 1.0000x reference)
#include <cuda_runtime.h>
#include <math.h>

#define NB 8
#define NN 4096
#define KK 30
#define FULLMASK 0xFFFFFFFFu

// Packed-pair fp32 helpers (sm_103a: FFMA2 only reachable via PTX f32x2)
#define FMA_F32X2(d, a, b) \
    asm("fma.rn.f32x2 %0, %1, %2, %0;" : "+l"(d) : "l"(a), "l"(b))
#define PACK2(d, lo, hi) \
    asm("mov.b64 %0, {%1, %2};" : "=l"(d) : "f"(lo), "f"(hi))
#define UNPACK2(lo, hi, d) \
    asm("mov.b64 {%0, %1}, %2;" : "=f"(lo), "=f"(hi) : "l"(d))

// scratch: knn indices (sorted by (pd desc, idx asc)), 8*4096*30 ints = 3.93 MB
__device__ int g_knn[NB * NN * KK];

// ---------------------------------------------------------------------------
// Kernel 1: exact top-30 KNN per row with JAX top_k tie-break semantics.
// One warp per query point. Top-30 list is warp-distributed: lane l (l<30)
// holds the rank-l key. Insertion = ballot + popc + shfl_up ripple (O(1)).
// Points stored in smem as float4 (x0, x1, x2, xx): 1 LDS.128 per candidate.
// ---------------------------------------------------------------------------
__global__ __launch_bounds__(256) void knn_kernel(const float* __restrict__ x) {
    extern __shared__ float4 sm4[];      // NN float4 = 64 KB

    int b     = blockIdx.x >> 9;            // 512 blocks per batch element
    int nbase = (blockIdx.x & 511) * 8;     // 8 rows (warps) per block
    const float* xb = x + (size_t)b * 3 * NN;

    for (int i = threadIdx.x; i < NN; i += 256) {
        float a0 = xb[i], a1 = xb[NN + i], a2 = xb[2 * NN + i];
        // replicate reference's non-fma reduction order: (x0*x0 + x1*x1) + x2*x2
        float xx = __fadd_rn(__fadd_rn(__fmul_rn(a0, a0), __fmul_rn(a1, a1)),
                             __fmul_rn(a2, a2));
        sm4[i] = make_float4(a0, a1, a2, xx);
    }
    __syncthreads();

    int warp = threadIdx.x >> 5;
    int lane = threadIdx.x & 31;
    int n = nbase + warp;

    float4 q = sm4[n];
    float cx = q.x, cy = q.y, cz = q.z, xxn = q.w;

    unsigned long long v = 0ULL;  // sentinel (all real keys are > 0)

    #pragma unroll 1
    for (int t = 0; t < NN / 32; ++t) {
        int m = t * 32 + lane;
        float4 c = sm4[m];                 // LDS.128, conflict-free
        // inner = (cx*x0 + cy*x1) + cz*x2   (no fma, matches reference path)
        float inr = __fadd_rn(__fadd_rn(__fmul_rn(cx, c.x), __fmul_rn(cy, c.y)),
                              __fmul_rn(cz, c.z));
        // pd = (2*inner - xx[m]) - xx[n]
        float pd = __fsub_rn(__fsub_rn(__fmul_rn(2.0f, inr), c.w), xxn);

        unsigned ou = __float_as_uint(pd);
        ou = (ou & 0x80000000u) ? ~ou : (ou | 0x80000000u);   // order-preserving map
        unsigned long long key =
            ((unsigned long long)ou << 32) | (unsigned long long)(0xFFFFFFFFu - (unsigned)m);

        unsigned long long thr = __shfl_sync(FULLMASK, v, 29);
        unsigned acc = __ballot_sync(FULLMASK, key > thr);
        while (acc) {
            int s = __ffs(acc) - 1;
            acc &= acc - 1;
            unsigned long long K = __shfl_sync(FULLMASK, key, s);
            thr = __shfl_sync(FULLMASK, v, 29);
            if (K > thr) {  // warp-uniform
                unsigned gt = __ballot_sync(FULLMASK, v > K) & 0x3FFFFFFFu;
                int pos = __popc(gt);
                unsigned long long up = __shfl_up_sync(FULLMASK, v, 1);
                if (lane < 30 && lane >= pos) v = (lane == pos) ? K : up;
            }
        }
    }

    if (lane < 30) {
        g_knn[((size_t)b * NN + n) * KK + lane] =
            (int)(0xFFFFFFFFu - (unsigned)(v & 0xFFFFFFFFull));
    }
}

// ---------------------------------------------------------------------------
// Kernel 2: fused edge-MLP + prefix softmax attention.
// Block = 256 threads = 8 warps = 8 points. Lane j<30 handles neighbor j.
// Both layers run on fma.rn.f32x2 (FFMA2):
//   L1: w1 transpose-packed  w1p[t*8+c] = (w1f[2t][c], w1f[2t+1][c]),
//       inputs replicated (v,v); bias pair loaded as u64 from contiguous b1.
//   L2: h1 packed pairwise; w2 rows read as ulonglong2 (LDS.128 broadcast).
// The three scales (k=10/20/30) share the nested neighbor prefix, so h2 is
// computed ONCE per neighbor; only the softmax weights differ.
// Output staged through smem so global stores are sector-dense (8 consecutive
// n per channel row) instead of 32-way scattered 4B stores.
// ---------------------------------------------------------------------------
#define SM_W1P  0        // 32 pair-rows * 8 u64 = 256 u64 = 512 floats
#define SM_B1   512
#define SM_W2F  576      // 64*64
#define SM_B2   4672
#define SM_WA   4736
#define SM_AB   4800
#define SM_H2   4832     // 8 * 64 * 33
#define SM_WGT  (4832 + 8*64*33)
#define SM_OUT  (SM_WGT + 8*32)   // 64 channels x 8 points
#define SM_TOT  (SM_OUT + 64*8)

__global__ __launch_bounds__(256, 2) void mlp_kernel(
    const float* __restrict__ x,
    const float* __restrict__ w1, const float* __restrict__ g1, const float* __restrict__ b1,
    const float* __restrict__ w2, const float* __restrict__ g2, const float* __restrict__ b2,
    const float* __restrict__ wa, const float* __restrict__ ba,
    const float* __restrict__ ga, const float* __restrict__ bga,
    float* __restrict__ out) {
    extern __shared__ float sm[];
    float* w1p  = sm + SM_W1P;   // viewed as u64 pairs: [t*8 + c]
    float* b1s  = sm + SM_B1;
    float* w2f  = sm + SM_W2F;
    float* b2s  = sm + SM_B2;
    float* was  = sm + SM_WA;
    float* abp  = sm + SM_AB;
    float* h2s  = sm + SM_H2;
    float* wgts = sm + SM_WGT;
    float* outs = sm + SM_OUT;

    int tid = threadIdx.x;
    float sq = sqrtf(1.0f + 1e-5f);

    // Fold BN eval scales into weights: h*(g/sq)+beta == (w*(g/sq))·f + beta
    // w1 is (64,6) row-major. Pack transposed pairs:
    //   w1p_u64[t*8+c] = ( w1[2t][c]*g1[2t]/sq , w1[2t+1][c]*g1[2t+1]/sq )
    {
        int t = tid >> 3, c = tid & 7;      // tid<256 -> t<32
        if (c < 6) {
            w1p[(t * 8 + c) * 2 + 0] = w1[(2 * t) * 6 + c]     * (g1[2 * t]     / sq);
            w1p[(t * 8 + c) * 2 + 1] = w1[(2 * t + 1) * 6 + c] * (g1[2 * t + 1] / sq);
        } else {
            w1p[(t * 8 + c) * 2 + 0] = 0.f;
            w1p[(t * 8 + c) * 2 + 1] = 0.f;
        }
    }
    for (int i = tid; i < 64 * 64; i += 256) {
        w2f[i] = w2[i] * (g2[i >> 6] / sq);
    }
    if (tid < 64) {
        b1s[tid] = b1[tid];
        b2s[tid] = b2[tid];
        was[tid] = wa[tid] * (ga[0] / sq);
    }
    if (tid == 0) abp[0] = (ga[0] / sq) * ba[0] + bga[0];
    __syncthreads();

    int p = tid >> 5;       // point within block
    int j = tid & 31;       // neighbor slot (j<30 active)
    int P = blockIdx.x * 8 + p;
    int b = P >> 12;
    int n = P & (NN - 1);
    const float* xb = x + (size_t)b * 3 * NN;

    float cx = xb[n], cy = xb[NN + n], cz = xb[2 * NN + n];
    float alog = 0.0f;

    if (j < 30) {
        int m = g_knn[(size_t)P * KK + j];
        float f0 = xb[m] - cx;
        float f1 = xb[NN + m] - cy;
        float f2 = xb[2 * NN + m] - cz;

        // Replicated packed inputs (v, v)
        unsigned long long in0, in1, in2, in3, in4, in5;
        PACK2(in0, f0, f0); PACK2(in1, f1, f1); PACK2(in2, f2, f2);
        PACK2(in3, cx, cx); PACK2(in4, cy, cy); PACK2(in5, cz, cz);

        const unsigned long long* w1pu = (const unsigned long long*)w1p;
        const unsigned long long* b1u  = (const unsigned long long*)b1s;

        // Layer 1: 64x6 as 32 output-pairs, each pair fully FFMA2.
        // Per-lane accumulation order == scalar version (b + w0*f0 + ... ).
        unsigned long long h1p[32];
        #pragma unroll
        for (int t = 0; t < 32; ++t) {
            const ulonglong2* wr = (const ulonglong2*)(w1pu + t * 8);
            unsigned long long acc = b1u[t];            // (b1[2t], b1[2t+1])
            ulonglong2 wA = wr[0];                      // c=0,1
            ulonglong2 wB = wr[1];                      // c=2,3
            ulonglong2 wC = wr[2];                      // c=4,5
            FMA_F32X2(acc, wA.x, in0);
            FMA_F32X2(acc, wA.y, in1);
            FMA_F32X2(acc, wB.x, in2);
            FMA_F32X2(acc, wB.y, in3);
            FMA_F32X2(acc, wC.x, in4);
            FMA_F32X2(acc, wC.y, in5);
            float a, d;
            UNPACK2(a, d, acc);
            float c0 = fmaxf(a, 0.2f * a);              // leaky relu (slope 0.2 > 0)
            float c1 = fmaxf(d, 0.2f * d);
            PACK2(h1p[t], c0, c1);
        }

        // Layer 2: 64x64 via FFMA2. Two packed accumulators preserve the
        // ((a0+a1)+(a2+a3)) reduction tree of the scalar version exactly:
        // accE over even pairs (elements 4i,4i+1), accO over odd (4i+2,4i+3).
        alog = abp[0];
        float* hrow = h2s + (p * 64) * 33 + j;
        #pragma unroll 2
        for (int o = 0; o < 64; ++o) {
            const ulonglong2* wr = (const ulonglong2*)(w2f + o * 64);
            unsigned long long accE = 0ULL, accO = 0ULL;   // packed (0.0f, 0.0f)
            #pragma unroll
            for (int i = 0; i < 16; ++i) {
                ulonglong2 w = wr[i];                       // LDS.128 broadcast
                FMA_F32X2(accE, w.x, h1p[2 * i]);
                FMA_F32X2(accO, w.y, h1p[2 * i + 1]);
            }
            float a0, a1, a2, a3;
            UNPACK2(a0, a1, accE);
            UNPACK2(a2, a3, accO);
            float a = ((a0 + a1) + (a2 + a3)) + b2s[o];
            float h2v = fmaxf(a, 0.2f * a);
            hrow[o * 33] = h2v;           // [p][o][j], j-stride 1, o-stride 33
            alog += was[o] * h2v;
        }
        // Reference: a = lrelu(bn(wa·h + ba)) BEFORE softmax. alog is the BN
        // output (scales folded), so apply the leaky relu here.
        alog = fmaxf(alog, 0.2f * alog);
    }

    // Prefix softmaxes over k = 10, 20, 30; collapse into one weight per j.
    float wgt = 0.f;
    #pragma unroll
    for (int kk = 1; kk <= 3; ++kk) {
        int K = 10 * kk;
        float xv = (j < K) ? alog : -INFINITY;
        float mx = xv;
        mx = fmaxf(mx, __shfl_xor_sync(FULLMASK, mx, 16));
        mx = fmaxf(mx, __shfl_xor_sync(FULLMASK, mx, 8));
        mx = fmaxf(mx, __shfl_xor_sync(FULLMASK, mx, 4));
        mx = fmaxf(mx, __shfl_xor_sync(FULLMASK, mx, 2));
        mx = fmaxf(mx, __shfl_xor_sync(FULLMASK, mx, 1));
        float e = (j < K) ? expf(alog - mx) : 0.f;
        float s = e;
        s += __shfl_xor_sync(FULLMASK, s, 16);
        s += __shfl_xor_sync(FULLMASK, s, 8);
        s += __shfl_xor_sync(FULLMASK, s, 4);
        s += __shfl_xor_sync(FULLMASK, s, 2);
        s += __shfl_xor_sync(FULLMASK, s, 1);
        wgt += e / s;
    }
    wgt *= (1.0f / 3.0f);
    wgts[p * 32 + j] = wgt;
    __syncwarp();

    // Reduce: res[c][p] = sum_j wgt[j] * h2[c][j]; lane covers c=j and c=j+32
    float acc0 = 0.f, acc1 = 0.f;
    const float* h0  = h2s + (p * 64 + j) * 33;        // bank: j*33 mod 32 == j
    const float* h1r = h2s + (p * 64 + j + 32) * 33;
    const float* wr  = wgts + p * 32;
    #pragma unroll
    for (int q = 0; q < 30; ++q) {
        float w = wr[q];
        acc0 += w * h0[q];
        acc1 += w * h1r[q];
    }
    outs[j * 8 + p]        = acc0;    // [c][p]
    outs[(j + 32) * 8 + p] = acc1;
    __syncthreads();

    // Coalesced store: each c-row writes 8 consecutive n (one full 32B sector).
    {
        int bb    = blockIdx.x >> 9;
        int nb    = (blockIdx.x & 511) * 8;
        int c  = tid >> 3;            // 0..31  (first half of channels)
        int pp = tid & 7;
        out[((size_t)bb * 64 + c) * NN + nb + pp]        = outs[c * 8 + pp];
        out[((size_t)bb * 64 + c + 32) * NN + nb + pp]   = outs[(c + 32) * 8 + pp];
    }
}

// ---------------------------------------------------------------------------

extern "C" void kernel_launch(void* const* d_in, const int* in_sizes, int n_in,
                              void* d_out, int out_size) {
    const float* x   = (const float*)d_in[0];
    const float* w1  = (const float*)d_in[1];
    const float* g1  = (const float*)d_in[2];
    const float* b1  = (const float*)d_in[3];
    const float* w2  = (const float*)d_in[4];
    const float* g2  = (const float*)d_in[5];
    const float* b2  = (const float*)d_in[6];
    const float* wa  = (const float*)d_in[7];
    const float* ba  = (const float*)d_in[8];
    const float* ga  = (const float*)d_in[9];
    const float* bga = (const float*)d_in[10];
    float* out = (float*)d_out;

    int knn_smem = NN * (int)sizeof(float4);      // 64 KB
    int mlp_smem = SM_TOT * (int)sizeof(float);   // ~90 KB

    cudaFuncSetAttribute(knn_kernel, cudaFuncAttributeMaxDynamicSharedMemorySize, knn_smem);
    cudaFuncSetAttribute(mlp_kernel, cudaFuncAttributeMaxDynamicSharedMemorySize, mlp_smem);

    knn_kernel<<<(NB * NN) / 8, 256, knn_smem>>>(x);
    mlp_kernel<<<(NB * NN) / 8, 256, mlp_smem>>>(x, w1, g1, b1, w2, g2, b2,
                                                 wa, ba, ga, bga, out);
}

// round 8
// speedup vs baseline: 1.0347x; 1.0347x over previous
#include <cuda_runtime.h>
#include <math.h>

#define NB 8
#define NN 4096
#define KK 30
#define FULLMASK 0xFFFFFFFFu

// Packed-pair fp32 helpers (sm_103a: FFMA2 only reachable via PTX f32x2)
#define FMA_F32X2(d, a, b) \
    asm("fma.rn.f32x2 %0, %1, %2, %0;" : "+l"(d) : "l"(a), "l"(b))
#define PACK2(d, lo, hi) \
    asm("mov.b64 %0, {%1, %2};" : "=l"(d) : "f"(lo), "f"(hi))
#define UNPACK2(lo, hi, d) \
    asm("mov.b64 {%0, %1}, %2;" : "=f"(lo), "=f"(hi) : "l"(d))

// scratch: knn indices (sorted by (pd desc, idx asc)), 8*4096*30 ints = 3.93 MB
__device__ int g_knn[NB * NN * KK];

// ---------------------------------------------------------------------------
// Kernel 1: exact top-30 KNN per row with JAX top_k tie-break semantics.
// One warp per query point. Top-30 list is warp-distributed: lane l (l<30)
// holds the rank-l key. Common path per tile: LDS.128 + 6 FP + 1 ballot
// against a float threshold register (rank-29 pd). Exactness of the float
// compare: scan is ascending-m, so any pd==thr candidate has larger m, i.e.
// a smaller (pd, -m) key than the incumbent -> correctly not inserted.
// ---------------------------------------------------------------------------
__global__ __launch_bounds__(256) void knn_kernel(const float* __restrict__ x) {
    extern __shared__ float4 sm4[];      // NN float4 = 64 KB

    int b     = blockIdx.x >> 9;            // 512 blocks per batch element
    int nbase = (blockIdx.x & 511) * 8;     // 8 rows (warps) per block
    const float* xb = x + (size_t)b * 3 * NN;

    for (int i = threadIdx.x; i < NN; i += 256) {
        float a0 = xb[i], a1 = xb[NN + i], a2 = xb[2 * NN + i];
        // replicate reference's non-fma reduction order: (x0*x0 + x1*x1) + x2*x2
        float xx = __fadd_rn(__fadd_rn(__fmul_rn(a0, a0), __fmul_rn(a1, a1)),
                             __fmul_rn(a2, a2));
        sm4[i] = make_float4(a0, a1, a2, xx);
    }
    __syncthreads();

    int warp = threadIdx.x >> 5;
    int lane = threadIdx.x & 31;
    int n = nbase + warp;

    float4 q = sm4[n];
    float cx = q.x, cy = q.y, cz = q.z, xxn = q.w;

    unsigned long long v = 0ULL;   // sentinel (all real keys are > 0)
    float thr = -INFINITY;         // pd of rank-29 entry (-inf while filling)

    #pragma unroll 1
    for (int t = 0; t < NN / 32; ++t) {
        int m = t * 32 + lane;
        float4 c = sm4[m];                 // LDS.128, conflict-free
        // inner = (cx*x0 + cy*x1) + cz*x2   (no fma, matches reference path)
        float inr = __fadd_rn(__fadd_rn(__fmul_rn(cx, c.x), __fmul_rn(cy, c.y)),
                              __fmul_rn(cz, c.z));
        // pd = (2*inner - xx[m]) - xx[n]
        float pd = __fsub_rn(__fsub_rn(__fmul_rn(2.0f, inr), c.w), xxn);

        unsigned insmask = __ballot_sync(FULLMASK, pd > thr);
        if (insmask) {                     // warp-uniform
            // order-preserving map + tie-break key (only on insertion tiles)
            unsigned ou = __float_as_uint(pd);
            ou = (ou & 0x80000000u) ? ~ou : (ou | 0x80000000u);
            unsigned long long key =
                ((unsigned long long)ou << 32) |
                (unsigned long long)(0xFFFFFFFFu - (unsigned)m);

            unsigned long long thrk = __shfl_sync(FULLMASK, v, 29);
            while (insmask) {
                int s = __ffs(insmask) - 1;
                insmask &= insmask - 1;
                unsigned long long K = __shfl_sync(FULLMASK, key, s);
                if (K > thrk) {            // warp-uniform (broadcast values)
                    unsigned gt = __ballot_sync(FULLMASK, v > K) & 0x3FFFFFFFu;
                    int pos = __popc(gt);
                    unsigned long long up = __shfl_up_sync(FULLMASK, v, 1);
                    if (lane < 30 && lane >= pos) v = (lane == pos) ? K : up;
                    thrk = __shfl_sync(FULLMASK, v, 29);
                }
            }
            // refresh float threshold from the (possibly new) rank-29 key
            unsigned hi = (unsigned)(thrk >> 32);
            if (hi) {   // hi==0 <=> sentinel (list not yet full) -> keep -inf
                unsigned ob = (hi & 0x80000000u) ? (hi & 0x7FFFFFFFu) : ~hi;
                thr = __uint_as_float(ob);
            }
        }
    }

    if (lane < 30) {
        g_knn[((size_t)b * NN + n) * KK + lane] =
            (int)(0xFFFFFFFFu - (unsigned)(v & 0xFFFFFFFFull));
    }
}

// ---------------------------------------------------------------------------
// Kernel 2: fused edge-MLP + prefix softmax attention.
// Block = 256 threads = 8 warps = 16 points: EACH WARP HANDLES 2 POINTS, so
// every broadcast LDS.128 of a w2 row-chunk feeds 4 FFMA2 (2 per point),
// halving smem-port traffic per point (the measured bottleneck: L1=89.5%).
// Lane j<30 handles neighbor j of both points. All-FFMA2 math, w2 BN-folded
// in smem; per-point arithmetic order identical to the measured R6 kernel.
// ---------------------------------------------------------------------------
#define SM_W1P  0        // 32 pair-rows * 8 u64 = 512 floats
#define SM_B1   512
#define SM_W2F  576      // 64*64
#define SM_B2   4672
#define SM_WA   4736
#define SM_AB   4800     // +4
#define SM_H2   4804     // 16 * 64 * 33
#define SM_WGT  (SM_H2 + 16*64*33)
#define SM_OUT  (SM_WGT + 16*32)   // [c][pl] : 64 x 16
#define SM_TOT  (SM_OUT + 64*16)

__global__ __launch_bounds__(256, 1) void mlp_kernel(
    const float* __restrict__ x,
    const float* __restrict__ w1, const float* __restrict__ g1, const float* __restrict__ b1,
    const float* __restrict__ w2, const float* __restrict__ g2, const float* __restrict__ b2,
    const float* __restrict__ wa, const float* __restrict__ ba,
    const float* __restrict__ ga, const float* __restrict__ bga,
    float* __restrict__ out) {
    extern __shared__ float sm[];
    float* w1p  = sm + SM_W1P;   // viewed as u64 pairs: [t*8 + c]
    float* b1s  = sm + SM_B1;
    float* w2f  = sm + SM_W2F;
    float* b2s  = sm + SM_B2;
    float* was  = sm + SM_WA;
    float* abp  = sm + SM_AB;
    float* h2s  = sm + SM_H2;
    float* wgts = sm + SM_WGT;
    float* outs = sm + SM_OUT;

    int tid = threadIdx.x;
    float sq = sqrtf(1.0f + 1e-5f);

    // Fold BN eval scales into weights: h*(g/sq)+beta == (w*(g/sq))·f + beta
    // w1 (64,6) row-major -> transpose-packed pairs:
    //   w1p_u64[t*8+c] = ( w1[2t][c]*g1[2t]/sq , w1[2t+1][c]*g1[2t+1]/sq )
    {
        int t = tid >> 3, c = tid & 7;      // tid<256 -> t<32
        if (c < 6) {
            w1p[(t * 8 + c) * 2 + 0] = w1[(2 * t) * 6 + c]     * (g1[2 * t]     / sq);
            w1p[(t * 8 + c) * 2 + 1] = w1[(2 * t + 1) * 6 + c] * (g1[2 * t + 1] / sq);
        } else {
            w1p[(t * 8 + c) * 2 + 0] = 0.f;
            w1p[(t * 8 + c) * 2 + 1] = 0.f;
        }
    }
    for (int i = tid; i < 64 * 64; i += 256) {
        w2f[i] = w2[i] * (g2[i >> 6] / sq);
    }
    if (tid < 64) {
        b1s[tid] = b1[tid];
        b2s[tid] = b2[tid];
        was[tid] = wa[tid] * (ga[0] / sq);
    }
    if (tid == 0) abp[0] = (ga[0] / sq) * ba[0] + bga[0];
    __syncthreads();

    int w = tid >> 5;       // warp -> handles local points 2w, 2w+1
    int j = tid & 31;       // neighbor slot (j<30 active)
    int plA = 2 * w, plB = 2 * w + 1;
    int PA = blockIdx.x * 16 + plA;
    int PB = PA + 1;
    int b  = PA >> 12;                    // 16 points never straddle batches
    int nA = PA & (NN - 1);
    int nB = nA + 1;
    const float* xb = x + (size_t)b * 3 * NN;

    float cxA = xb[nA], cyA = xb[NN + nA], czA = xb[2 * NN + nA];
    float cxB = xb[nB], cyB = xb[NN + nB], czB = xb[2 * NN + nB];
    float alogA = 0.0f, alogB = 0.0f;

    if (j < 30) {
        int mA = g_knn[(size_t)PA * KK + j];
        int mB = g_knn[(size_t)PB * KK + j];
        float fA0 = xb[mA] - cxA, fA1 = xb[NN + mA] - cyA, fA2 = xb[2 * NN + mA] - czA;
        float fB0 = xb[mB] - cxB, fB1 = xb[NN + mB] - cyB, fB2 = xb[2 * NN + mB] - czB;

        const unsigned long long* w1pu = (const unsigned long long*)w1p;
        const unsigned long long* b1u  = (const unsigned long long*)b1s;

        // ---- Layer 1 for point A ----
        unsigned long long iA0, iA1, iA2, iA3, iA4, iA5;
        PACK2(iA0, fA0, fA0); PACK2(iA1, fA1, fA1); PACK2(iA2, fA2, fA2);
        PACK2(iA3, cxA, cxA); PACK2(iA4, cyA, cyA); PACK2(iA5, czA, czA);
        unsigned long long h1A[32];
        #pragma unroll
        for (int t = 0; t < 32; ++t) {
            const ulonglong2* wr = (const ulonglong2*)(w1pu + t * 8);
            unsigned long long acc = b1u[t];
            ulonglong2 wA = wr[0], wB = wr[1], wC = wr[2];
            FMA_F32X2(acc, wA.x, iA0); FMA_F32X2(acc, wA.y, iA1);
            FMA_F32X2(acc, wB.x, iA2); FMA_F32X2(acc, wB.y, iA3);
            FMA_F32X2(acc, wC.x, iA4); FMA_F32X2(acc, wC.y, iA5);
            float a, d;
            UNPACK2(a, d, acc);
            float c0 = fmaxf(a, 0.2f * a);
            float c1 = fmaxf(d, 0.2f * d);
            PACK2(h1A[t], c0, c1);
        }

        // ---- Layer 1 for point B ----
        unsigned long long iB0, iB1, iB2, iB3, iB4, iB5;
        PACK2(iB0, fB0, fB0); PACK2(iB1, fB1, fB1); PACK2(iB2, fB2, fB2);
        PACK2(iB3, cxB, cxB); PACK2(iB4, cyB, cyB); PACK2(iB5, czB, czB);
        unsigned long long h1B[32];
        #pragma unroll
        for (int t = 0; t < 32; ++t) {
            const ulonglong2* wr = (const ulonglong2*)(w1pu + t * 8);
            unsigned long long acc = b1u[t];
            ulonglong2 wA = wr[0], wB = wr[1], wC = wr[2];
            FMA_F32X2(acc, wA.x, iB0); FMA_F32X2(acc, wA.y, iB1);
            FMA_F32X2(acc, wB.x, iB2); FMA_F32X2(acc, wB.y, iB3);
            FMA_F32X2(acc, wC.x, iB4); FMA_F32X2(acc, wC.y, iB5);
            float a, d;
            UNPACK2(a, d, acc);
            float c0 = fmaxf(a, 0.2f * a);
            float c1 = fmaxf(d, 0.2f * d);
            PACK2(h1B[t], c0, c1);
        }

        // ---- Layer 2 (shared w2 loads feed both points) ----
        alogA = abp[0]; alogB = abp[0];
        float* hrowA = h2s + (plA * 64) * 33 + j;
        float* hrowB = h2s + (plB * 64) * 33 + j;
        #pragma unroll 2
        for (int o = 0; o < 64; ++o) {
            const ulonglong2* wr = (const ulonglong2*)(w2f + o * 64);
            unsigned long long aEA = 0ULL, aOA = 0ULL, aEB = 0ULL, aOB = 0ULL;
            #pragma unroll
            for (int i = 0; i < 16; ++i) {
                ulonglong2 ww = wr[i];                      // LDS.128 broadcast
                FMA_F32X2(aEA, ww.x, h1A[2 * i]);
                FMA_F32X2(aOA, ww.y, h1A[2 * i + 1]);
                FMA_F32X2(aEB, ww.x, h1B[2 * i]);
                FMA_F32X2(aOB, ww.y, h1B[2 * i + 1]);
            }
            float a0, a1, a2, a3, bb2 = b2s[o];
            UNPACK2(a0, a1, aEA); UNPACK2(a2, a3, aOA);
            float aA = ((a0 + a1) + (a2 + a3)) + bb2;
            float hA = fmaxf(aA, 0.2f * aA);
            UNPACK2(a0, a1, aEB); UNPACK2(a2, a3, aOB);
            float aB = ((a0 + a1) + (a2 + a3)) + bb2;
            float hB = fmaxf(aB, 0.2f * aB);
            hrowA[o * 33] = hA;
            hrowB[o * 33] = hB;
            float wav = was[o];
            alogA += wav * hA;
            alogB += wav * hB;
        }
        // Reference applies lrelu to the attention logit BEFORE softmax.
        alogA = fmaxf(alogA, 0.2f * alogA);
        alogB = fmaxf(alogB, 0.2f * alogB);
    }

    // Prefix softmaxes over k = 10, 20, 30 for both points.
    float wgtA = 0.f, wgtB = 0.f;
    #pragma unroll
    for (int kk = 1; kk <= 3; ++kk) {
        int K = 10 * kk;
        float xA = (j < K) ? alogA : -INFINITY;
        float xB = (j < K) ? alogB : -INFINITY;
        float mA = xA, mB = xB;
        #pragma unroll
        for (int d = 16; d; d >>= 1) {
            mA = fmaxf(mA, __shfl_xor_sync(FULLMASK, mA, d));
            mB = fmaxf(mB, __shfl_xor_sync(FULLMASK, mB, d));
        }
        float eA = (j < K) ? expf(alogA - mA) : 0.f;
        float eB = (j < K) ? expf(alogB - mB) : 0.f;
        float sA = eA, sB = eB;
        #pragma unroll
        for (int d = 16; d; d >>= 1) {
            sA += __shfl_xor_sync(FULLMASK, sA, d);
            sB += __shfl_xor_sync(FULLMASK, sB, d);
        }
        wgtA += eA / sA;
        wgtB += eB / sB;
    }
    wgtA *= (1.0f / 3.0f);
    wgtB *= (1.0f / 3.0f);
    wgts[plA * 32 + j] = wgtA;
    wgts[plB * 32 + j] = wgtB;
    __syncwarp();

    // Reduce both points: res[c][pl] = sum_j wgt[j]*h2[c][j]; lane covers c=j, c=j+32
    #pragma unroll
    for (int s = 0; s < 2; ++s) {
        int pl = 2 * w + s;
        float acc0 = 0.f, acc1 = 0.f;
        const float* h0  = h2s + (pl * 64 + j) * 33;       // bank j+q: conflict-free
        const float* h1r = h2s + (pl * 64 + j + 32) * 33;
        const float* wr  = wgts + pl * 32;
        #pragma unroll
        for (int q = 0; q < 30; ++q) {
            float ww = wr[q];
            acc0 += ww * h0[q];
            acc1 += ww * h1r[q];
        }
        outs[j * 16 + pl]        = acc0;   // [c][pl]
        outs[(j + 32) * 16 + pl] = acc1;
    }
    __syncthreads();

    // Coalesced store: 4 consecutive points per thread as one float4 (16B),
    // 4 threads per channel -> 64B contiguous per channel row.
    {
        int bb = blockIdx.x >> 8;            // 256 blocks per batch element
        int nb = (blockIdx.x & 255) * 16;
        int c  = tid >> 2;                   // 0..63
        int qq = (tid & 3) * 4;
        float4 v = *(const float4*)(outs + c * 16 + qq);
        *(float4*)(out + ((size_t)bb * 64 + c) * NN + nb + qq) = v;
    }
}

// ---------------------------------------------------------------------------

extern "C" void kernel_launch(void* const* d_in, const int* in_sizes, int n_in,
                              void* d_out, int out_size) {
    const float* x   = (const float*)d_in[0];
    const float* w1  = (const float*)d_in[1];
    const float* g1  = (const float*)d_in[2];
    const float* b1  = (const float*)d_in[3];
    const float* w2  = (const float*)d_in[4];
    const float* g2  = (const float*)d_in[5];
    const float* b2  = (const float*)d_in[6];
    const float* wa  = (const float*)d_in[7];
    const float* ba  = (const float*)d_in[8];
    const float* ga  = (const float*)d_in[9];
    const float* bga = (const float*)d_in[10];
    float* out = (float*)d_out;

    int knn_smem = NN * (int)sizeof(float4);      // 64 KB
    int mlp_smem = SM_TOT * (int)sizeof(float);   // ~157 KB

    cudaFuncSetAttribute(knn_kernel, cudaFuncAttributeMaxDynamicSharedMemorySize, knn_smem);
    cudaFuncSetAttribute(mlp_kernel, cudaFuncAttributeMaxDynamicSharedMemorySize, mlp_smem);

    knn_kernel<<<(NB * NN) / 8, 256, knn_smem>>>(x);
    mlp_kernel<<<(NB * NN) / 16, 256, mlp_smem>>>(x, w1, g1, b1, w2, g2, b2,
                                                  wa, ba, ga, bga, out);
}

// round 11
// speedup vs baseline: 1.0603x; 1.0247x over previous
#include <cuda_runtime.h>
#include <math.h>

#define NB 8
#define NN 4096
#define KK 30
#define FULLMASK 0xFFFFFFFFu

// Packed-pair fp32 helpers (sm_103a: FFMA2 only reachable via PTX f32x2)
#define FMA_F32X2(d, a, b) \
    asm("fma.rn.f32x2 %0, %1, %2, %0;" : "+l"(d) : "l"(a), "l"(b))
#define PACK2(d, lo, hi) \
    asm("mov.b64 %0, {%1, %2};" : "=l"(d) : "f"(lo), "f"(hi))
#define UNPACK2(lo, hi, d) \
    asm("mov.b64 {%0, %1}, %2;" : "=f"(lo), "=f"(hi) : "l"(d))

// scratch: knn indices (sorted by (pd desc, idx asc)), 8*4096*30 ints = 3.93 MB
__device__ int g_knn[NB * NN * KK];

// ---------------------------------------------------------------------------
// Kernel 1: exact top-30 KNN, one warp per query point, warp-distributed list.
// 4-tile batching: common path per 128 candidates = 4 independent
// LDS.128->FP chains (ILP 4) + ONE ballot on the combined predicate. Per-tile
// ballots + key packing + ripple insert only on super-tiles containing a
// candidate above the rank-29 threshold (~130 events per row).
// Float-threshold exactness: scan is ascending-m, so a candidate with
// pd == thr has m larger than every list entry -> its (pd, -m) key is smaller
// than the rank-29 key -> correctly excluded by the strict > compare.
// ---------------------------------------------------------------------------
__global__ __launch_bounds__(256) void knn_kernel(const float* __restrict__ x) {
    extern __shared__ float4 sm4[];      // NN float4 = 64 KB

    int b     = blockIdx.x >> 9;            // 512 blocks per batch element
    int nbase = (blockIdx.x & 511) * 8;     // 8 rows (warps) per block
    const float* xb = x + (size_t)b * 3 * NN;

    for (int i = threadIdx.x; i < NN; i += 256) {
        float a0 = xb[i], a1 = xb[NN + i], a2 = xb[2 * NN + i];
        // replicate reference's non-fma reduction order: (x0*x0 + x1*x1) + x2*x2
        float xx = __fadd_rn(__fadd_rn(__fmul_rn(a0, a0), __fmul_rn(a1, a1)),
                             __fmul_rn(a2, a2));
        sm4[i] = make_float4(a0, a1, a2, xx);
    }
    __syncthreads();

    int warp = threadIdx.x >> 5;
    int lane = threadIdx.x & 31;
    int n = nbase + warp;

    float4 q = sm4[n];
    float cx = q.x, cy = q.y, cz = q.z, xxn = q.w;

    unsigned long long v = 0ULL;   // sentinel (all real keys are > 0)
    float thr = -INFINITY;         // pd of rank-29 entry (-inf while filling)

    #pragma unroll 1
    for (int t = 0; t < NN / 128; ++t) {
        int m0 = t * 128 + lane;
        // 4 independent distance chains (ILP to hide LDS + FP latency)
        float4 c0 = sm4[m0];
        float4 c1 = sm4[m0 + 32];
        float4 c2 = sm4[m0 + 64];
        float4 c3 = sm4[m0 + 96];
        float i0 = __fadd_rn(__fadd_rn(__fmul_rn(cx, c0.x), __fmul_rn(cy, c0.y)), __fmul_rn(cz, c0.z));
        float i1 = __fadd_rn(__fadd_rn(__fmul_rn(cx, c1.x), __fmul_rn(cy, c1.y)), __fmul_rn(cz, c1.z));
        float i2 = __fadd_rn(__fadd_rn(__fmul_rn(cx, c2.x), __fmul_rn(cy, c2.y)), __fmul_rn(cz, c2.z));
        float i3 = __fadd_rn(__fadd_rn(__fmul_rn(cx, c3.x), __fmul_rn(cy, c3.y)), __fmul_rn(cz, c3.z));
        float pd0 = __fsub_rn(__fsub_rn(__fmul_rn(2.0f, i0), c0.w), xxn);
        float pd1 = __fsub_rn(__fsub_rn(__fmul_rn(2.0f, i1), c1.w), xxn);
        float pd2 = __fsub_rn(__fsub_rn(__fmul_rn(2.0f, i2), c2.w), xxn);
        float pd3 = __fsub_rn(__fsub_rn(__fmul_rn(2.0f, i3), c3.w), xxn);

        bool hit = (pd0 > thr) | (pd1 > thr) | (pd2 > thr) | (pd3 > thr);
        if (__ballot_sync(FULLMASK, hit)) {      // warp-uniform rare path
            #pragma unroll
            for (int s = 0; s < 4; ++s) {
                float pd = (s == 0) ? pd0 : (s == 1) ? pd1 : (s == 2) ? pd2 : pd3;
                int   m  = m0 + s * 32;
                unsigned insmask = __ballot_sync(FULLMASK, pd > thr);
                if (insmask) {
                    unsigned ou = __float_as_uint(pd);
                    ou = (ou & 0x80000000u) ? ~ou : (ou | 0x80000000u);
                    unsigned long long key =
                        ((unsigned long long)ou << 32) |
                        (unsigned long long)(0xFFFFFFFFu - (unsigned)m);

                    unsigned long long thrk = __shfl_sync(FULLMASK, v, 29);
                    while (insmask) {
                        int sl = __ffs(insmask) - 1;
                        insmask &= insmask - 1;
                        unsigned long long K = __shfl_sync(FULLMASK, key, sl);
                        if (K > thrk) {          // warp-uniform
                            unsigned gt = __ballot_sync(FULLMASK, v > K) & 0x3FFFFFFFu;
                            int pos = __popc(gt);
                            unsigned long long up = __shfl_up_sync(FULLMASK, v, 1);
                            if (lane < 30 && lane >= pos) v = (lane == pos) ? K : up;
                            thrk = __shfl_sync(FULLMASK, v, 29);
                        }
                    }
                    unsigned hi = (unsigned)(thrk >> 32);
                    if (hi) {    // hi==0 <=> list not yet full -> keep -inf
                        unsigned ob = (hi & 0x80000000u) ? (hi & 0x7FFFFFFFu) : ~hi;
                        thr = __uint_as_float(ob);
                    }
                }
            }
        }
    }

    if (lane < 30) {
        g_knn[((size_t)b * NN + n) * KK + lane] =
            (int)(0xFFFFFFFFu - (unsigned)(v & 0xFFFFFFFFull));
    }
}

// ---------------------------------------------------------------------------
// Kernel 2: fused edge-MLP + prefix softmax attention.
// Block = 256 threads = 8 warps = 16 points (2 points per warp: each w2
// broadcast LDS feeds 4 FFMA2 -> halved crossbar traffic, verified by
// L1 89.5%->52.1% in R8). o-loop unroll 4 deepens the in-flight LDS window:
// occupancy is 8 warps/SM (reg+smem-bound), so latency must be hidden by ILP.
// ---------------------------------------------------------------------------
#define SM_W1P  0        // 32 pair-rows * 8 u64 = 512 floats
#define SM_B1   512
#define SM_W2F  576      // 64*64
#define SM_B2   4672
#define SM_WA   4736
#define SM_AB   4800     // +4
#define SM_H2   4804     // 16 * 64 * 33
#define SM_WGT  (SM_H2 + 16*64*33)
#define SM_OUT  (SM_WGT + 16*32)   // [c][pl] : 64 x 16
#define SM_TOT  (SM_OUT + 64*16)

__global__ __launch_bounds__(256, 1) void mlp_kernel(
    const float* __restrict__ x,
    const float* __restrict__ w1, const float* __restrict__ g1, const float* __restrict__ b1,
    const float* __restrict__ w2, const float* __restrict__ g2, const float* __restrict__ b2,
    const float* __restrict__ wa, const float* __restrict__ ba,
    const float* __restrict__ ga, const float* __restrict__ bga,
    float* __restrict__ out) {
    extern __shared__ float sm[];
    float* w1p  = sm + SM_W1P;
    float* b1s  = sm + SM_B1;
    float* w2f  = sm + SM_W2F;
    float* b2s  = sm + SM_B2;
    float* was  = sm + SM_WA;
    float* abp  = sm + SM_AB;
    float* h2s  = sm + SM_H2;
    float* wgts = sm + SM_WGT;
    float* outs = sm + SM_OUT;

    int tid = threadIdx.x;
    float sq = sqrtf(1.0f + 1e-5f);

    {
        int t = tid >> 3, c = tid & 7;      // tid<256 -> t<32
        if (c < 6) {
            w1p[(t * 8 + c) * 2 + 0] = w1[(2 * t) * 6 + c]     * (g1[2 * t]     / sq);
            w1p[(t * 8 + c) * 2 + 1] = w1[(2 * t + 1) * 6 + c] * (g1[2 * t + 1] / sq);
        } else {
            w1p[(t * 8 + c) * 2 + 0] = 0.f;
            w1p[(t * 8 + c) * 2 + 1] = 0.f;
        }
    }
    for (int i = tid; i < 64 * 64; i += 256) {
        w2f[i] = w2[i] * (g2[i >> 6] / sq);
    }
    if (tid < 64) {
        b1s[tid] = b1[tid];
        b2s[tid] = b2[tid];
        was[tid] = wa[tid] * (ga[0] / sq);
    }
    if (tid == 0) abp[0] = (ga[0] / sq) * ba[0] + bga[0];
    __syncthreads();

    int w = tid >> 5;       // warp -> handles local points 2w, 2w+1
    int j = tid & 31;       // neighbor slot (j<30 active)
    int plA = 2 * w, plB = 2 * w + 1;
    int PA = blockIdx.x * 16 + plA;
    int PB = PA + 1;
    int b  = PA >> 12;
    int nA = PA & (NN - 1);
    int nB = nA + 1;
    const float* xb = x + (size_t)b * 3 * NN;

    float cxA = xb[nA], cyA = xb[NN + nA], czA = xb[2 * NN + nA];
    float cxB = xb[nB], cyB = xb[NN + nB], czB = xb[2 * NN + nB];
    float alogA = 0.0f, alogB = 0.0f;

    if (j < 30) {
        int mA = g_knn[(size_t)PA * KK + j];
        int mB = g_knn[(size_t)PB * KK + j];
        float fA0 = xb[mA] - cxA, fA1 = xb[NN + mA] - cyA, fA2 = xb[2 * NN + mA] - czA;
        float fB0 = xb[mB] - cxB, fB1 = xb[NN + mB] - cyB, fB2 = xb[2 * NN + mB] - czB;

        const unsigned long long* w1pu = (const unsigned long long*)w1p;
        const unsigned long long* b1u  = (const unsigned long long*)b1s;

        unsigned long long iA0, iA1, iA2, iA3, iA4, iA5;
        PACK2(iA0, fA0, fA0); PACK2(iA1, fA1, fA1); PACK2(iA2, fA2, fA2);
        PACK2(iA3, cxA, cxA); PACK2(iA4, cyA, cyA); PACK2(iA5, czA, czA);
        unsigned long long h1A[32];
        #pragma unroll
        for (int t = 0; t < 32; ++t) {
            const ulonglong2* wr = (const ulonglong2*)(w1pu + t * 8);
            unsigned long long acc = b1u[t];
            ulonglong2 wA = wr[0], wB = wr[1], wC = wr[2];
            FMA_F32X2(acc, wA.x, iA0); FMA_F32X2(acc, wA.y, iA1);
            FMA_F32X2(acc, wB.x, iA2); FMA_F32X2(acc, wB.y, iA3);
            FMA_F32X2(acc, wC.x, iA4); FMA_F32X2(acc, wC.y, iA5);
            float a, d;
            UNPACK2(a, d, acc);
            float c0 = fmaxf(a, 0.2f * a);
            float c1 = fmaxf(d, 0.2f * d);
            PACK2(h1A[t], c0, c1);
        }

        unsigned long long iB0, iB1, iB2, iB3, iB4, iB5;
        PACK2(iB0, fB0, fB0); PACK2(iB1, fB1, fB1); PACK2(iB2, fB2, fB2);
        PACK2(iB3, cxB, cxB); PACK2(iB4, cyB, cyB); PACK2(iB5, czB, czB);
        unsigned long long h1B[32];
        #pragma unroll
        for (int t = 0; t < 32; ++t) {
            const ulonglong2* wr = (const ulonglong2*)(w1pu + t * 8);
            unsigned long long acc = b1u[t];
            ulonglong2 wA = wr[0], wB = wr[1], wC = wr[2];
            FMA_F32X2(acc, wA.x, iB0); FMA_F32X2(acc, wA.y, iB1);
            FMA_F32X2(acc, wB.x, iB2); FMA_F32X2(acc, wB.y, iB3);
            FMA_F32X2(acc, wC.x, iB4); FMA_F32X2(acc, wC.y, iB5);
            float a, d;
            UNPACK2(a, d, acc);
            float c0 = fmaxf(a, 0.2f * a);
            float c1 = fmaxf(d, 0.2f * d);
            PACK2(h1B[t], c0, c1);
        }

        // ---- Layer 2 (shared w2 loads feed both points), deep unroll ----
        alogA = abp[0]; alogB = abp[0];
        float* hrowA = h2s + (plA * 64) * 33 + j;
        float* hrowB = h2s + (plB * 64) * 33 + j;
        #pragma unroll 4
        for (int o = 0; o < 64; ++o) {
            const ulonglong2* wr = (const ulonglong2*)(w2f + o * 64);
            unsigned long long aEA = 0ULL, aOA = 0ULL, aEB = 0ULL, aOB = 0ULL;
            #pragma unroll
            for (int i = 0; i < 16; ++i) {
                ulonglong2 ww = wr[i];                      // LDS.128 broadcast
                FMA_F32X2(aEA, ww.x, h1A[2 * i]);
                FMA_F32X2(aOA, ww.y, h1A[2 * i + 1]);
                FMA_F32X2(aEB, ww.x, h1B[2 * i]);
                FMA_F32X2(aOB, ww.y, h1B[2 * i + 1]);
            }
            float a0, a1, a2, a3, bb2 = b2s[o];
            UNPACK2(a0, a1, aEA); UNPACK2(a2, a3, aOA);
            float aA = ((a0 + a1) + (a2 + a3)) + bb2;
            float hA = fmaxf(aA, 0.2f * aA);
            UNPACK2(a0, a1, aEB); UNPACK2(a2, a3, aOB);
            float aB = ((a0 + a1) + (a2 + a3)) + bb2;
            float hB = fmaxf(aB, 0.2f * aB);
            hrowA[o * 33] = hA;
            hrowB[o * 33] = hB;
            float wav = was[o];
            alogA += wav * hA;
            alogB += wav * hB;
        }
        alogA = fmaxf(alogA, 0.2f * alogA);
        alogB = fmaxf(alogB, 0.2f * alogB);
    }

    float wgtA = 0.f, wgtB = 0.f;
    #pragma unroll
    for (int kk = 1; kk <= 3; ++kk) {
        int K = 10 * kk;
        float xA = (j < K) ? alogA : -INFINITY;
        float xB = (j < K) ? alogB : -INFINITY;
        float mA = xA, mB = xB;
        #pragma unroll
        for (int d = 16; d; d >>= 1) {
            mA = fmaxf(mA, __shfl_xor_sync(FULLMASK, mA, d));
            mB = fmaxf(mB, __shfl_xor_sync(FULLMASK, mB, d));
        }
        float eA = (j < K) ? expf(alogA - mA) : 0.f;
        float eB = (j < K) ? expf(alogB - mB) : 0.f;
        float sA = eA, sB = eB;
        #pragma unroll
        for (int d = 16; d; d >>= 1) {
            sA += __shfl_xor_sync(FULLMASK, sA, d);
            sB += __shfl_xor_sync(FULLMASK, sB, d);
        }
        wgtA += eA / sA;
        wgtB += eB / sB;
    }
    wgtA *= (1.0f / 3.0f);
    wgtB *= (1.0f / 3.0f);
    wgts[plA * 32 + j] = wgtA;
    wgts[plB * 32 + j] = wgtB;
    __syncwarp();

    #pragma unroll
    for (int s = 0; s < 2; ++s) {
        int pl = 2 * w + s;
        float acc0 = 0.f, acc1 = 0.f;
        const float* h0  = h2s + (pl * 64 + j) * 33;
        const float* h1r = h2s + (pl * 64 + j + 32) * 33;
        const float* wr  = wgts + pl * 32;
        #pragma unroll
        for (int qd = 0; qd < 30; ++qd) {
            float ww = wr[qd];
            acc0 += ww * h0[qd];
            acc1 += ww * h1r[qd];
        }
        outs[j * 16 + pl]        = acc0;   // [c][pl]
        outs[(j + 32) * 16 + pl] = acc1;
    }
    __syncthreads();

    {
        int bb = blockIdx.x >> 8;            // 256 blocks per batch element
        int nb = (blockIdx.x & 255) * 16;
        int c  = tid >> 2;                   // 0..63
        int qq = (tid & 3) * 4;
        float4 v = *(const float4*)(outs + c * 16 + qq);
        *(float4*)(out + ((size_t)bb * 64 + c) * NN + nb + qq) = v;
    }
}

// ---------------------------------------------------------------------------

extern "C" void kernel_launch(void* const* d_in, const int* in_sizes, int n_in,
                              void* d_out, int out_size) {
    const float* x   = (const float*)d_in[0];
    const float* w1  = (const float*)d_in[1];
    const float* g1  = (const float*)d_in[2];
    const float* b1  = (const float*)d_in[3];
    const float* w2  = (const float*)d_in[4];
    const float* g2  = (const float*)d_in[5];
    const float* b2  = (const float*)d_in[6];
    const float* wa  = (const float*)d_in[7];
    const float* ba  = (const float*)d_in[8];
    const float* ga  = (const float*)d_in[9];
    const float* bga = (const float*)d_in[10];
    float* out = (float*)d_out;

    int knn_smem = NN * (int)sizeof(float4);      // 64 KB
    int mlp_smem = SM_TOT * (int)sizeof(float);   // ~157 KB

    cudaFuncSetAttribute(knn_kernel, cudaFuncAttributeMaxDynamicSharedMemorySize, knn_smem);
    cudaFuncSetAttribute(mlp_kernel, cudaFuncAttributeMaxDynamicSharedMemorySize, mlp_smem);

    knn_kernel<<<(NB * NN) / 8, 256, knn_smem>>>(x);
    mlp_kernel<<<(NB * NN) / 16, 256, mlp_smem>>>(x, w1, g1, b1, w2, g2, b2,
                                                  wa, ba, ga, bga, out);
}